// round 8
// baseline (speedup 1.0000x reference)
#include <cuda_runtime.h>
#include <cuda_fp16.h>
#include <cstdint>

#define NTOK 32768
#define HDIM 768
#define NEXP 8
#define TM 128
#define MAXTILES (NTOK / TM + NEXP)  // 264

// GEMM tiles
#define CTM 128
#define CTN 128
#define CTK 64                        // halves per k-stage
#define KT  (HDIM / CTK)              // 12 stages
#define NSTG 3
#define ROWB 144                      // padded row stride bytes (64 halves + 16 pad)
#define TILEB (128 * ROWB)            // 18432 bytes per (128 x 64) half tile
#define STAGEB (2 * TILEB)            // Ah, Bh = 36864
#define SMEM_BYTES (NSTG * STAGEB)    // 110592 -> 2 CTAs/SM (221KB dyn) fits 228KB

typedef unsigned long long u64;

// ---------------- scratch ----------------
__device__ int   g_eid[2][NTOK];
__device__ float g_wt [2][NTOK];
__device__ int   g_cnt[2][NEXP];
__device__ int   g_cur[2][NEXP];
__device__ int   g_off[2][NEXP + 1];
__device__ int   g_ts [2][NEXP + 1];
__device__ int   g_bucket[2][NTOK];
__device__ float g_bw[2][NTOK];

__device__ __half g_xh[NTOK * HDIM];
__device__ __half g_wh[NEXP * HDIM * HDIM];

// ---------------- helpers ----------------
__device__ __forceinline__ void cpa16(uint32_t s, const void* g) {
    asm volatile("cp.async.cg.shared.global [%0], [%1], 16;" :: "r"(s), "l"(g));
}
__device__ __forceinline__ void cp_commit() { asm volatile("cp.async.commit_group;"); }
template <int N> __device__ __forceinline__ void cp_wait() {
    asm volatile("cp.async.wait_group %0;" :: "n"(N));
}
__device__ __forceinline__ void mma16816_f32(float* c, const uint32_t* a, const uint32_t* b) {
    asm volatile(
        "mma.sync.aligned.m16n8k16.row.col.f32.f16.f16.f32 "
        "{%0,%1,%2,%3}, {%4,%5,%6,%7}, {%8,%9}, {%0,%1,%2,%3};"
        : "+f"(c[0]), "+f"(c[1]), "+f"(c[2]), "+f"(c[3])
        : "r"(a[0]), "r"(a[1]), "r"(a[2]), "r"(a[3]), "r"(b[0]), "r"(b[1]));
}
__device__ __forceinline__ void ldsm4(uint32_t* r, uint32_t addr) {
    asm volatile("ldmatrix.sync.aligned.m8n8.x4.shared.b16 {%0,%1,%2,%3}, [%4];"
        : "=r"(r[0]), "=r"(r[1]), "=r"(r[2]), "=r"(r[3]) : "r"(addr));
}

// ---------------- convert weights (fp32 -> fp16 hi) + zero counters ----------------
__global__ __launch_bounds__(256) void convw_kernel(const float* __restrict__ w) {
    if (blockIdx.x == 0 && threadIdx.x < 2 * NEXP) {
        ((int*)g_cnt)[threadIdx.x] = 0;
        ((int*)g_cur)[threadIdx.x] = 0;
    }
    int i = blockIdx.x * 256 + threadIdx.x;       // one float4 per thread
    float4 v = ((const float4*)w)[i];
    __half2 h0 = __floats2half2_rn(v.x, v.y);
    __half2 h1 = __floats2half2_rn(v.z, v.w);
    ((__half2*)g_wh)[2 * i] = h0;
    ((__half2*)g_wh)[2 * i + 1] = h1;
}

// ---------------- kernel 1: router (fused x hi conversion, float4 path) ----------------
__global__ __launch_bounds__(256) void router_kernel(
    const float* __restrict__ x, const float* __restrict__ rw, const float* __restrict__ rb)
{
    __shared__ float s_rw[NEXP * HDIM];
    for (int i = threadIdx.x; i < NEXP * HDIM; i += 256) s_rw[i] = rw[i];
    __syncthreads();

    int warp = threadIdx.x >> 5, lane = threadIdx.x & 31;
    int tok = (blockIdx.x << 3) + warp;
    const float4* xr = (const float4*)(x + (size_t)tok * HDIM);
    __half2* xh = (__half2*)(g_xh + (size_t)tok * HDIM);

    float acc[NEXP];
#pragma unroll
    for (int e = 0; e < NEXP; e++) acc[e] = 0.f;
#pragma unroll
    for (int i = 0; i < HDIM / 128; i++) {        // 6 iters of float4
        int idx = i * 32 + lane;
        float4 v = xr[idx];
        xh[2 * idx]     = __floats2half2_rn(v.x, v.y);
        xh[2 * idx + 1] = __floats2half2_rn(v.z, v.w);
#pragma unroll
        for (int e = 0; e < NEXP; e++) {
            float4 w4 = ((const float4*)(s_rw + e * HDIM))[idx];
            acc[e] = fmaf(v.x, w4.x, fmaf(v.y, w4.y, fmaf(v.z, w4.z, fmaf(v.w, w4.w, acc[e]))));
        }
    }
#pragma unroll
    for (int e = 0; e < NEXP; e++)
#pragma unroll
        for (int o = 16; o > 0; o >>= 1)
            acc[e] += __shfl_xor_sync(0xffffffffu, acc[e], o);

    if (lane == 0) {
        float s[NEXP];
#pragma unroll
        for (int e = 0; e < NEXP; e++) s[e] = acc[e] + rb[e];
        float m = s[0];
#pragma unroll
        for (int e = 1; e < NEXP; e++) m = fmaxf(m, s[e]);
        float p[NEXP]; float Z = 0.f;
#pragma unroll
        for (int e = 0; e < NEXP; e++) { p[e] = expf(s[e] - m); Z += p[e]; }
        int e0 = 0;
#pragma unroll
        for (int e = 1; e < NEXP; e++) if (p[e] > p[e0]) e0 = e;
        int e1 = (e0 == 0) ? 1 : 0;
#pragma unroll
        for (int e = 0; e < NEXP; e++) if (e != e0 && p[e] > p[e1]) e1 = e;
        float p0 = p[e0] / Z, p1 = p[e1] / Z;
        float inv = 1.f / (p0 + p1 + 1e-9f);
        g_eid[0][tok] = e0; g_wt[0][tok] = p0 * inv;
        g_eid[1][tok] = e1; g_wt[1][tok] = p1 * inv;
        atomicAdd(&g_cnt[0][e0], 1);
        atomicAdd(&g_cnt[1][e1], 1);
    }
}

// ---------------- kernel 2: scan ----------------
__global__ void scan_kernel() {
    if (threadIdx.x == 0 && blockIdx.x == 0) {
        for (int s = 0; s < 2; s++) {
            int o = 0, t = 0;
            for (int e = 0; e < NEXP; e++) {
                g_off[s][e] = o; g_ts[s][e] = t;
                o += g_cnt[s][e];
                t += (g_cnt[s][e] + TM - 1) >> 7;
            }
            g_off[s][NEXP] = o; g_ts[s][NEXP] = t;
        }
    }
}

// ---------------- kernel 3: scatter ----------------
__global__ __launch_bounds__(256) void scatter_kernel() {
    int t = blockIdx.x * 256 + threadIdx.x;
    if (t >= NTOK) return;
#pragma unroll
    for (int s = 0; s < 2; s++) {
        int e = g_eid[s][t];
        int pos = g_off[s][e] + atomicAdd(&g_cur[s][e], 1);
        g_bucket[s][pos] = t;
        g_bw[s][pos] = g_wt[s][t];
    }
}

// ---------------- kernel 4: grouped GEMM, fp16 -> f32 accum, 2 CTAs/SM, CTK=64 ----------------
template <int SLOT, bool ACC>
__global__ __launch_bounds__(256, 2)
void moe_mma(const float* __restrict__ eb, float* __restrict__ out)
{
    extern __shared__ __align__(128) char smem[];
    const uint32_t sb = (uint32_t)__cvta_generic_to_shared(smem);

    __shared__ int   sMeta[3];
    __shared__ int   sTok[CTM];
    __shared__ float sWgt[CTM];
    __shared__ float sBias[CTN];

    int tid = threadIdx.x;
    int wid = tid >> 5, lane = tid & 31;

    if (tid == 0) {
        int bx = blockIdx.x;
        if (bx >= g_ts[SLOT][NEXP]) sMeta[0] = -1;
        else {
            int e = 0;
            while (g_ts[SLOT][e + 1] <= bx) e++;
            sMeta[0] = e;
            sMeta[1] = g_off[SLOT][e] + ((bx - g_ts[SLOT][e]) << 7);
            sMeta[2] = g_off[SLOT][e + 1];
        }
    }
    __syncthreads();
    int e = sMeta[0];
    if (e < 0) return;
    int m0 = sMeta[1], mEnd = sMeta[2];
    int nBase = blockIdx.y << 7;   // * 128

    if (tid < CTM) {
        int p = m0 + tid;
        int pc = p < mEnd ? p : mEnd - 1;
        sTok[tid] = g_bucket[SLOT][pc];
        sWgt[tid] = g_bw[SLOT][pc];
        sBias[tid] = __ldg(eb + e * HDIM + nBase + tid);
    }
    __syncthreads();

    // ---- stage loader: 8 cp.async(16B) per thread (Ah 4 + Bh 4) ----
    int lrow = tid >> 1;                 // 0..127
    int lc0  = (tid & 1) * 4;            // chunks 0-3 or 4-7
    size_t gAr = (size_t)sTok[lrow] * HDIM;
    size_t gBr = ((size_t)e * HDIM + nBase + lrow) * HDIM;

    auto load_stage = [&](int kt, int buf) {
        uint32_t sbase = sb + (uint32_t)buf * STAGEB;
        int kc = kt * CTK;
#pragma unroll
        for (int t = 0; t < 4; t++) {
            int c = lc0 + t;
            uint32_t so = (uint32_t)(lrow * ROWB + c * 16);
            cpa16(sbase + 0 * TILEB + so, g_xh + gAr + kc + c * 8);
            cpa16(sbase + 1 * TILEB + so, g_wh + gBr + kc + c * 8);
        }
    };

    load_stage(0, 0); cp_commit();
    load_stage(1, 1); cp_commit();

    int warp_m = wid >> 1, warp_n = wid & 1;
    int r = lane >> 2, q = lane & 3;

    // ldmatrix lane address offsets (bytes within a tile)
    uint32_t aOff = (uint32_t)((warp_m * 32 + (lane & 15)) * ROWB + ((lane >> 4) << 4));
    uint32_t bOff = (uint32_t)((warp_n * 64 + ((lane >> 4) << 3) + (lane & 7)) * ROWB
                               + (((lane >> 3) & 1) << 4));

    float acc[2][8][4];
#pragma unroll
    for (int mt = 0; mt < 2; mt++)
#pragma unroll
        for (int nt = 0; nt < 8; nt++)
#pragma unroll
            for (int i = 0; i < 4; i++) acc[mt][nt][i] = 0.f;

    for (int kt = 0; kt < KT; kt++) {
        int buf = kt % NSTG;
        if (kt == KT - 1) cp_wait<0>(); else cp_wait<1>();
        __syncthreads();
        if (kt + 2 < KT) { load_stage(kt + 2, (kt + 2) % NSTG); cp_commit(); }

        uint32_t tb = sb + (uint32_t)buf * STAGEB;

#pragma unroll
        for (int k16 = 0; k16 < 4; k16++) {
            uint32_t kb = (uint32_t)(k16 * 32);
            uint32_t ah[2][4], bh[8][2];
#pragma unroll
            for (int mt = 0; mt < 2; mt++)
                ldsm4(ah[mt], tb + aOff + (uint32_t)(mt * 16 * ROWB) + kb);
#pragma unroll
            for (int ntp = 0; ntp < 4; ntp++) {
                uint32_t regs[4];
                ldsm4(regs, tb + TILEB + bOff + (uint32_t)(ntp * 16 * ROWB) + kb);
                bh[2 * ntp][0] = regs[0]; bh[2 * ntp][1] = regs[1];
                bh[2 * ntp + 1][0] = regs[2]; bh[2 * ntp + 1][1] = regs[3];
            }
#pragma unroll
            for (int mt = 0; mt < 2; mt++)
#pragma unroll
                for (int nt = 0; nt < 8; nt++)
                    mma16816_f32(acc[mt][nt], ah[mt], bh[nt]);
        }
    }

    // ---- epilogue ----
#pragma unroll
    for (int mt = 0; mt < 2; mt++) {
        int lr0 = warp_m * 32 + mt * 16 + r;
        int lr1 = lr0 + 8;
        bool v0 = (m0 + lr0) < mEnd;
        bool v1 = (m0 + lr1) < mEnd;
        float w0 = sWgt[lr0], w1 = sWgt[lr1];
        float* o0 = out + (size_t)sTok[lr0] * HDIM + nBase;
        float* o1 = out + (size_t)sTok[lr1] * HDIM + nBase;
#pragma unroll
        for (int nt = 0; nt < 8; nt++) {
            int lc = warp_n * 64 + nt * 8 + 2 * q;
            float bx = sBias[lc], by = sBias[lc + 1];
            if (v0) {
                float2 v;
                v.x = w0 * (acc[mt][nt][0] + bx);
                v.y = w0 * (acc[mt][nt][1] + by);
                float2* dst = (float2*)(o0 + lc);
                if (ACC) { float2 o = *dst; o.x += v.x; o.y += v.y; *dst = o; }
                else *dst = v;
            }
            if (v1) {
                float2 v;
                v.x = w1 * (acc[mt][nt][2] + bx);
                v.y = w1 * (acc[mt][nt][3] + by);
                float2* dst = (float2*)(o1 + lc);
                if (ACC) { float2 o = *dst; o.x += v.x; o.y += v.y; *dst = o; }
                else *dst = v;
            }
        }
    }
}

// ---------------- launch ----------------
extern "C" void kernel_launch(void* const* d_in, const int* in_sizes, int n_in,
                              void* d_out, int out_size)
{
    const float* x  = (const float*)d_in[0];
    const float* rw = (const float*)d_in[1];
    const float* rb = (const float*)d_in[2];
    const float* ew = (const float*)d_in[3];
    const float* eb = (const float*)d_in[4];
    float* out = (float*)d_out;
    (void)in_sizes; (void)n_in; (void)out_size;

    cudaFuncSetAttribute(moe_mma<0, false>, cudaFuncAttributeMaxDynamicSharedMemorySize, SMEM_BYTES);
    cudaFuncSetAttribute(moe_mma<1, true >, cudaFuncAttributeMaxDynamicSharedMemorySize, SMEM_BYTES);

    convw_kernel<<<NEXP * HDIM * HDIM / 1024, 256>>>(ew);
    router_kernel<<<NTOK / 8, 256>>>(x, rw, rb);
    scan_kernel<<<1, 32>>>();
    scatter_kernel<<<NTOK / 256, 256>>>();
    moe_mma<0, false><<<dim3(MAXTILES, HDIM / CTN), 256, SMEM_BYTES>>>(eb, out);
    moe_mma<1, true ><<<dim3(MAXTILES, HDIM / CTN), 256, SMEM_BYTES>>>(eb, out);
}

// round 10
// speedup vs baseline: 1.2374x; 1.2374x over previous
#include <cuda_runtime.h>
#include <cuda_fp16.h>
#include <cstdint>

#define NTOK 32768
#define HDIM 768
#define NEXP 8
#define NPAIR 28
#define TM 128
#define MAXT2 (NTOK / TM + NPAIR)    // 284

// GEMM tiles (r7-proven mainloop config)
#define CTM 128
#define CTK 32                        // halves per k-stage
#define KT  (HDIM / CTK)              // 24 stages
#define NSTG 4
#define ROWB 80                       // padded row stride bytes
#define TILEB (128 * ROWB)            // 10240
#define STAGEB (2 * TILEB)            // A tile + B tile (64 rows expert a + 64 rows expert b)
#define SMEM_BYTES (NSTG * STAGEB)    // 81920 -> 2 CTAs/SM

typedef unsigned long long u64;

// ---------------- scratch ----------------
__device__ int   g_eid[2][NTOK];
__device__ float g_wt [2][NTOK];
__device__ int   g_cnt[NPAIR];
__device__ int   g_cur[NPAIR];
__device__ int   g_off[NPAIR + 1];
__device__ int   g_ts [NPAIR + 1];
__device__ int   g_bucket[NTOK];
__device__ float g_wa[NTOK];
__device__ float g_wb[NTOK];

__device__ __half g_xh[NTOK * HDIM];
__device__ __half g_wh[NEXP * HDIM * HDIM];

// ---------------- helpers ----------------
__device__ __forceinline__ void cpa16(uint32_t s, const void* g) {
    asm volatile("cp.async.cg.shared.global [%0], [%1], 16;" :: "r"(s), "l"(g));
}
__device__ __forceinline__ void cp_commit() { asm volatile("cp.async.commit_group;"); }
template <int N> __device__ __forceinline__ void cp_wait() {
    asm volatile("cp.async.wait_group %0;" :: "n"(N));
}
__device__ __forceinline__ void mma16816_f32(float* c, const uint32_t* a, const uint32_t* b) {
    asm volatile(
        "mma.sync.aligned.m16n8k16.row.col.f32.f16.f16.f32 "
        "{%0,%1,%2,%3}, {%4,%5,%6,%7}, {%8,%9}, {%0,%1,%2,%3};"
        : "+f"(c[0]), "+f"(c[1]), "+f"(c[2]), "+f"(c[3])
        : "r"(a[0]), "r"(a[1]), "r"(a[2]), "r"(a[3]), "r"(b[0]), "r"(b[1]));
}
__device__ __forceinline__ void ldsm4(uint32_t* r, uint32_t addr) {
    asm volatile("ldmatrix.sync.aligned.m8n8.x4.shared.b16 {%0,%1,%2,%3}, [%4];"
        : "=r"(r[0]), "=r"(r[1]), "=r"(r[2]), "=r"(r[3]) : "r"(addr));
}
__device__ __forceinline__ int pair_id(int a, int b) {   // a < b
    return a * (2 * NEXP - 1 - a) / 2 + (b - a - 1);
}

// ---------------- convert weights (fp32 -> fp16 hi) + zero counters ----------------
__global__ __launch_bounds__(256) void convw_kernel(const float* __restrict__ w) {
    if (blockIdx.x == 0 && threadIdx.x < 2 * NPAIR) {
        if (threadIdx.x < NPAIR) g_cnt[threadIdx.x] = 0;
        else g_cur[threadIdx.x - NPAIR] = 0;
    }
    int i = blockIdx.x * 256 + threadIdx.x;       // one float4 per thread
    float4 v = ((const float4*)w)[i];
    ((__half2*)g_wh)[2 * i]     = __floats2half2_rn(v.x, v.y);
    ((__half2*)g_wh)[2 * i + 1] = __floats2half2_rn(v.z, v.w);
}

// ---------------- kernel 1: router (fused x hi conversion) ----------------
__global__ __launch_bounds__(256) void router_kernel(
    const float* __restrict__ x, const float* __restrict__ rw, const float* __restrict__ rb)
{
    __shared__ float s_rw[NEXP * HDIM];
    for (int i = threadIdx.x; i < NEXP * HDIM; i += 256) s_rw[i] = rw[i];
    __syncthreads();

    int warp = threadIdx.x >> 5, lane = threadIdx.x & 31;
    int tok = (blockIdx.x << 3) + warp;
    const float4* xr = (const float4*)(x + (size_t)tok * HDIM);
    __half2* xh = (__half2*)(g_xh + (size_t)tok * HDIM);

    float acc[NEXP];
#pragma unroll
    for (int e = 0; e < NEXP; e++) acc[e] = 0.f;
#pragma unroll
    for (int i = 0; i < HDIM / 128; i++) {
        int idx = i * 32 + lane;
        float4 v = xr[idx];
        xh[2 * idx]     = __floats2half2_rn(v.x, v.y);
        xh[2 * idx + 1] = __floats2half2_rn(v.z, v.w);
#pragma unroll
        for (int e = 0; e < NEXP; e++) {
            float4 w4 = ((const float4*)(s_rw + e * HDIM))[idx];
            acc[e] = fmaf(v.x, w4.x, fmaf(v.y, w4.y, fmaf(v.z, w4.z, fmaf(v.w, w4.w, acc[e]))));
        }
    }
#pragma unroll
    for (int e = 0; e < NEXP; e++)
#pragma unroll
        for (int o = 16; o > 0; o >>= 1)
            acc[e] += __shfl_xor_sync(0xffffffffu, acc[e], o);

    if (lane == 0) {
        float s[NEXP];
#pragma unroll
        for (int e = 0; e < NEXP; e++) s[e] = acc[e] + rb[e];
        float m = s[0];
#pragma unroll
        for (int e = 1; e < NEXP; e++) m = fmaxf(m, s[e]);
        float p[NEXP]; float Z = 0.f;
#pragma unroll
        for (int e = 0; e < NEXP; e++) { p[e] = expf(s[e] - m); Z += p[e]; }
        int e0 = 0;
#pragma unroll
        for (int e = 1; e < NEXP; e++) if (p[e] > p[e0]) e0 = e;
        int e1 = (e0 == 0) ? 1 : 0;
#pragma unroll
        for (int e = 0; e < NEXP; e++) if (e != e0 && p[e] > p[e1]) e1 = e;
        float p0 = p[e0] / Z, p1 = p[e1] / Z;
        float inv = 1.f / (p0 + p1 + 1e-9f);
        g_eid[0][tok] = e0; g_wt[0][tok] = p0 * inv;
        g_eid[1][tok] = e1; g_wt[1][tok] = p1 * inv;
        int a = min(e0, e1), b = max(e0, e1);
        atomicAdd(&g_cnt[pair_id(a, b)], 1);
    }
}

// ---------------- kernel 2: scan ----------------
__global__ void scan_kernel() {
    if (threadIdx.x == 0 && blockIdx.x == 0) {
        int o = 0, t = 0;
        for (int p = 0; p < NPAIR; p++) {
            g_off[p] = o; g_ts[p] = t;
            o += g_cnt[p];
            t += (g_cnt[p] + TM - 1) >> 7;
        }
        g_off[NPAIR] = o; g_ts[NPAIR] = t;
    }
}

// ---------------- kernel 3: scatter (by expert pair) ----------------
__global__ __launch_bounds__(256) void scatter_kernel() {
    int t = blockIdx.x * 256 + threadIdx.x;
    if (t >= NTOK) return;
    int e0 = g_eid[0][t], e1 = g_eid[1][t];
    float w0 = g_wt[0][t], w1 = g_wt[1][t];
    int a = min(e0, e1), b = max(e0, e1);
    float wa = (e0 < e1) ? w0 : w1;
    float wb = (e0 < e1) ? w1 : w0;
    int p = pair_id(a, b);
    int pos = g_off[p] + atomicAdd(&g_cur[p], 1);
    g_bucket[pos] = t;
    g_wa[pos] = wa;
    g_wb[pos] = wb;
}

// ---------------- kernel 4: pair GEMM — both experts, single out write ----------------
__global__ __launch_bounds__(256, 2)
void moe_pair(const float* __restrict__ eb, float* __restrict__ out)
{
    extern __shared__ __align__(128) char smem[];
    const uint32_t sb = (uint32_t)__cvta_generic_to_shared(smem);

    __shared__ int   sMeta[3];
    __shared__ int   sTok[CTM];
    __shared__ float sWa[CTM];
    __shared__ float sWb[CTM];
    __shared__ float sBias[128];   // 64 cols expert a + 64 cols expert b

    int tid = threadIdx.x;
    int wid = tid >> 5, lane = tid & 31;

    if (tid == 0) {
        int bx = blockIdx.x;
        if (bx >= g_ts[NPAIR]) sMeta[0] = -1;
        else {
            int p = 0;
            while (g_ts[p + 1] <= bx) p++;
            sMeta[0] = p;
            sMeta[1] = g_off[p] + ((bx - g_ts[p]) << 7);
            sMeta[2] = g_off[p + 1];
        }
    }
    __syncthreads();
    int p = sMeta[0];
    if (p < 0) return;
    int m0 = sMeta[1], mEnd = sMeta[2];
    // decode pair -> (ea, eb_)
    int ea = 0, rem = p, span = NEXP - 1;
    while (rem >= span) { rem -= span; ea++; span--; }
    int eb_ = ea + 1 + rem;
    int nBase = blockIdx.y << 6;   // * 64

    if (tid < CTM) {
        int pp = m0 + tid;
        int pc = pp < mEnd ? pp : mEnd - 1;
        sTok[tid] = g_bucket[pc];
        sWa[tid]  = g_wa[pc];
        sWb[tid]  = g_wb[pc];
    }
    if (tid < 128) {
        int ex = (tid < 64) ? ea : eb_;
        sBias[tid] = __ldg(eb + ex * HDIM + nBase + (tid & 63));
    }
    __syncthreads();

    // ---- stage loader: A rows = tokens; B rows 0-63 expert a cols, 64-127 expert b ----
    int lrow = tid >> 1;                 // 0..127
    int lc0  = (tid & 1) * 2;            // chunk 0 or 2 (of 4 x 16B per 32-half row)
    size_t gAr = (size_t)sTok[lrow] * HDIM;
    int bexp = (lrow < 64) ? ea : eb_;
    size_t gBr = ((size_t)bexp * HDIM + nBase + (lrow & 63)) * HDIM;

    auto load_stage = [&](int kt, int buf) {
        uint32_t sbase = sb + (uint32_t)buf * STAGEB;
        int kc = kt * CTK;
#pragma unroll
        for (int t = 0; t < 2; t++) {
            int c = lc0 + t;
            uint32_t so = (uint32_t)(lrow * ROWB + c * 16);
            cpa16(sbase + 0 * TILEB + so, g_xh + gAr + kc + c * 8);
            cpa16(sbase + 1 * TILEB + so, g_wh + gBr + kc + c * 8);
        }
    };

    load_stage(0, 0); cp_commit();
    load_stage(1, 1); cp_commit();
    load_stage(2, 2); cp_commit();

    int warp_m = wid >> 1, warp_n = wid & 1;   // warp: M32 x N32 (per expert)
    int r = lane >> 2, q = lane & 3;

    uint32_t aOff = (uint32_t)((warp_m * 32 + (lane & 15)) * ROWB + ((lane >> 4) << 4));
    // B lane offset within a 16-row group (same pattern as before)
    uint32_t bLane = (uint32_t)((((lane >> 4) << 3) + (lane & 7)) * ROWB
                                + (((lane >> 3) & 1) << 4));

    float acc[2][2][4][4];   // [expert][mt][nt][frag]
#pragma unroll
    for (int x = 0; x < 2; x++)
#pragma unroll
        for (int mt = 0; mt < 2; mt++)
#pragma unroll
            for (int nt = 0; nt < 4; nt++)
#pragma unroll
                for (int i = 0; i < 4; i++) acc[x][mt][nt][i] = 0.f;

    for (int kt = 0; kt < KT; kt++) {
        int buf = kt & 3;
        if (kt <= KT - 3) cp_wait<2>();
        else if (kt == KT - 2) cp_wait<1>();
        else cp_wait<0>();
        __syncthreads();
        if (kt + 3 < KT) { load_stage(kt + 3, (kt + 3) & 3); cp_commit(); }

        uint32_t tb = sb + (uint32_t)buf * STAGEB;

#pragma unroll
        for (int k16 = 0; k16 < 2; k16++) {
            uint32_t kb = (uint32_t)(k16 * 32);
            uint32_t ah[2][4], bf[2][4][2];
#pragma unroll
            for (int mt = 0; mt < 2; mt++)
                ldsm4(ah[mt], tb + aOff + (uint32_t)(mt * 16 * ROWB) + kb);
#pragma unroll
            for (int x = 0; x < 2; x++)
#pragma unroll
                for (int ntp = 0; ntp < 2; ntp++) {
                    uint32_t regs[4];
                    uint32_t grpRow = (uint32_t)((x * 64 + warp_n * 32 + ntp * 16) * ROWB);
                    ldsm4(regs, tb + TILEB + bLane + grpRow + kb);
                    bf[x][2 * ntp][0] = regs[0]; bf[x][2 * ntp][1] = regs[1];
                    bf[x][2 * ntp + 1][0] = regs[2]; bf[x][2 * ntp + 1][1] = regs[3];
                }
#pragma unroll
            for (int x = 0; x < 2; x++)
#pragma unroll
                for (int mt = 0; mt < 2; mt++)
#pragma unroll
                    for (int nt = 0; nt < 4; nt++)
                        mma16816_f32(acc[x][mt][nt], ah[mt], bf[x][nt]);
        }
    }

    // ---- epilogue: out = wa*(ya+ba) + wb*(yb+bb), single write ----
#pragma unroll
    for (int mt = 0; mt < 2; mt++) {
        int lr0 = warp_m * 32 + mt * 16 + r;
        int lr1 = lr0 + 8;
        bool v0 = (m0 + lr0) < mEnd;
        bool v1 = (m0 + lr1) < mEnd;
        float wa0 = sWa[lr0], wb0 = sWb[lr0];
        float wa1 = sWa[lr1], wb1 = sWb[lr1];
        float* o0 = out + (size_t)sTok[lr0] * HDIM + nBase;
        float* o1 = out + (size_t)sTok[lr1] * HDIM + nBase;
#pragma unroll
        for (int nt = 0; nt < 4; nt++) {
            int lc = warp_n * 32 + nt * 8 + 2 * q;
            float bax = sBias[lc], bay = sBias[lc + 1];
            float bbx = sBias[64 + lc], bby = sBias[64 + lc + 1];
            if (v0) {
                float2 v;
                v.x = wa0 * (acc[0][mt][nt][0] + bax) + wb0 * (acc[1][mt][nt][0] + bbx);
                v.y = wa0 * (acc[0][mt][nt][1] + bay) + wb0 * (acc[1][mt][nt][1] + bby);
                *(float2*)(o0 + lc) = v;
            }
            if (v1) {
                float2 v;
                v.x = wa1 * (acc[0][mt][nt][2] + bax) + wb1 * (acc[1][mt][nt][2] + bbx);
                v.y = wa1 * (acc[0][mt][nt][3] + bay) + wb1 * (acc[1][mt][nt][3] + bby);
                *(float2*)(o1 + lc) = v;
            }
        }
    }
}

// ---------------- launch ----------------
extern "C" void kernel_launch(void* const* d_in, const int* in_sizes, int n_in,
                              void* d_out, int out_size)
{
    const float* x  = (const float*)d_in[0];
    const float* rw = (const float*)d_in[1];
    const float* rb = (const float*)d_in[2];
    const float* ew = (const float*)d_in[3];
    const float* eb = (const float*)d_in[4];
    float* out = (float*)d_out;
    (void)in_sizes; (void)n_in; (void)out_size;

    cudaFuncSetAttribute(moe_pair, cudaFuncAttributeMaxDynamicSharedMemorySize, SMEM_BYTES);

    convw_kernel<<<NEXP * HDIM * HDIM / 1024, 256>>>(ew);
    router_kernel<<<NTOK / 8, 256>>>(x, rw, rb);
    scan_kernel<<<1, 32>>>();
    scatter_kernel<<<NTOK / 256, 256>>>();
    moe_pair<<<dim3(MAXT2, HDIM / 64), 256, SMEM_BYTES>>>(eb, out);
}

// round 11
// speedup vs baseline: 1.2994x; 1.0501x over previous
#include <cuda_runtime.h>
#include <cuda_fp16.h>
#include <cstdint>

#define NTOK 32768
#define HDIM 768
#define NEXP 8
#define NPAIR 28
#define TM 128
#define MAXT2 (NTOK / TM + NPAIR)    // 284

// GEMM tiles (proven mainloop config)
#define CTM 128
#define CTK 32
#define KT  (HDIM / CTK)              // 24 stages
#define NSTG 4
#define ROWB 80
#define TILEB (128 * ROWB)            // 10240
#define STAGEB (2 * TILEB)
#define SMEM_BYTES (NSTG * STAGEB)    // 81920 -> 2 CTAs/SM

#define RBLK (NTOK / 8)               // 4096 router blocks
#define WBLK (NEXP * HDIM * HDIM / 1024)  // 4608 convert blocks

typedef unsigned long long u64;

// ---------------- scratch ----------------
__device__ int   g_cnt [NPAIR];       // zero-init at load; scan re-zeros each replay
__device__ int   g_mend[NPAIR];
__device__ int   g_ts  [NPAIR + 1];
__device__ int   g_tok [NPAIR][NTOK];
__device__ float g_pwa [NPAIR][NTOK];
__device__ float g_pwb [NPAIR][NTOK];

__device__ __half g_xh[NTOK * HDIM];
__device__ __half g_wh[NEXP * HDIM * HDIM];

// ---------------- helpers ----------------
__device__ __forceinline__ void cpa16(uint32_t s, const void* g) {
    asm volatile("cp.async.cg.shared.global [%0], [%1], 16;" :: "r"(s), "l"(g));
}
__device__ __forceinline__ void cp_commit() { asm volatile("cp.async.commit_group;"); }
template <int N> __device__ __forceinline__ void cp_wait() {
    asm volatile("cp.async.wait_group %0;" :: "n"(N));
}
__device__ __forceinline__ void mma16816_f32(float* c, const uint32_t* a, const uint32_t* b) {
    asm volatile(
        "mma.sync.aligned.m16n8k16.row.col.f32.f16.f16.f32 "
        "{%0,%1,%2,%3}, {%4,%5,%6,%7}, {%8,%9}, {%0,%1,%2,%3};"
        : "+f"(c[0]), "+f"(c[1]), "+f"(c[2]), "+f"(c[3])
        : "r"(a[0]), "r"(a[1]), "r"(a[2]), "r"(a[3]), "r"(b[0]), "r"(b[1]));
}
__device__ __forceinline__ void ldsm4(uint32_t* r, uint32_t addr) {
    asm volatile("ldmatrix.sync.aligned.m8n8.x4.shared.b16 {%0,%1,%2,%3}, [%4];"
        : "=r"(r[0]), "=r"(r[1]), "=r"(r[2]), "=r"(r[3]) : "r"(addr));
}
__device__ __forceinline__ int pair_id(int a, int b) {   // a < b
    return a * (2 * NEXP - 1 - a) / 2 + (b - a - 1);
}

// ---------------- kernel 1: fused prep — router blocks + weight-convert blocks ----------------
__global__ __launch_bounds__(256) void prep_kernel(
    const float* __restrict__ x, const float* __restrict__ rw,
    const float* __restrict__ rb, const float* __restrict__ w)
{
    if (blockIdx.x >= RBLK) {
        // ---- weight convert path ----
        int i = (blockIdx.x - RBLK) * 256 + threadIdx.x;   // one float4 per thread
        float4 v = ((const float4*)w)[i];
        ((__half2*)g_wh)[2 * i]     = __floats2half2_rn(v.x, v.y);
        ((__half2*)g_wh)[2 * i + 1] = __floats2half2_rn(v.z, v.w);
        return;
    }

    // ---- router path (fused x hi conversion + direct bucket write) ----
    __shared__ float s_rw[NEXP * HDIM];
    for (int i = threadIdx.x; i < NEXP * HDIM; i += 256) s_rw[i] = rw[i];
    __syncthreads();

    int warp = threadIdx.x >> 5, lane = threadIdx.x & 31;
    int tok = (blockIdx.x << 3) + warp;
    const float4* xr = (const float4*)(x + (size_t)tok * HDIM);
    __half2* xh = (__half2*)(g_xh + (size_t)tok * HDIM);

    float acc[NEXP];
#pragma unroll
    for (int e = 0; e < NEXP; e++) acc[e] = 0.f;
#pragma unroll
    for (int i = 0; i < HDIM / 128; i++) {
        int idx = i * 32 + lane;
        float4 v = xr[idx];
        xh[2 * idx]     = __floats2half2_rn(v.x, v.y);
        xh[2 * idx + 1] = __floats2half2_rn(v.z, v.w);
#pragma unroll
        for (int e = 0; e < NEXP; e++) {
            float4 w4 = ((const float4*)(s_rw + e * HDIM))[idx];
            acc[e] = fmaf(v.x, w4.x, fmaf(v.y, w4.y, fmaf(v.z, w4.z, fmaf(v.w, w4.w, acc[e]))));
        }
    }
#pragma unroll
    for (int e = 0; e < NEXP; e++)
#pragma unroll
        for (int o = 16; o > 0; o >>= 1)
            acc[e] += __shfl_xor_sync(0xffffffffu, acc[e], o);

    if (lane == 0) {
        float s[NEXP];
#pragma unroll
        for (int e = 0; e < NEXP; e++) s[e] = acc[e] + rb[e];
        float m = s[0];
#pragma unroll
        for (int e = 1; e < NEXP; e++) m = fmaxf(m, s[e]);
        float p[NEXP]; float Z = 0.f;
#pragma unroll
        for (int e = 0; e < NEXP; e++) { p[e] = expf(s[e] - m); Z += p[e]; }
        int e0 = 0;
#pragma unroll
        for (int e = 1; e < NEXP; e++) if (p[e] > p[e0]) e0 = e;
        int e1 = (e0 == 0) ? 1 : 0;
#pragma unroll
        for (int e = 0; e < NEXP; e++) if (e != e0 && p[e] > p[e1]) e1 = e;
        float p0 = p[e0] / Z, p1 = p[e1] / Z;
        float inv = 1.f / (p0 + p1 + 1e-9f);
        int a = min(e0, e1), b = max(e0, e1);
        float wa = (e0 < e1) ? p0 * inv : p1 * inv;
        float wb = (e0 < e1) ? p1 * inv : p0 * inv;
        int pid = pair_id(a, b);
        int pos = atomicAdd(&g_cnt[pid], 1);
        g_tok[pid][pos] = tok;
        g_pwa[pid][pos] = wa;
        g_pwb[pid][pos] = wb;
    }
}

// ---------------- kernel 2: scan (+ counter snapshot & reset for replay safety) ----------------
__global__ void scan_kernel() {
    if (threadIdx.x == 0 && blockIdx.x == 0) {
        int t = 0;
        for (int p = 0; p < NPAIR; p++) {
            g_ts[p] = t;
            int c = g_cnt[p];
            g_mend[p] = c;
            g_cnt[p] = 0;                // reset for next graph replay
            t += (c + TM - 1) >> 7;
        }
        g_ts[NPAIR] = t;
    }
}

// ---------------- kernel 3: pair GEMM — both experts, single out write ----------------
__global__ __launch_bounds__(256, 2)
void moe_pair(const float* __restrict__ eb, float* __restrict__ out)
{
    extern __shared__ __align__(128) char smem[];
    const uint32_t sb = (uint32_t)__cvta_generic_to_shared(smem);

    __shared__ int   sMeta[3];
    __shared__ int   sTok[CTM];
    __shared__ float sWa[CTM];
    __shared__ float sWb[CTM];
    __shared__ float sBias[128];

    int tid = threadIdx.x;
    int wid = tid >> 5, lane = tid & 31;

    if (tid == 0) {
        int bx = blockIdx.x;
        if (bx >= g_ts[NPAIR]) sMeta[0] = -1;
        else {
            int p = 0;
            while (g_ts[p + 1] <= bx) p++;
            sMeta[0] = p;
            sMeta[1] = (bx - g_ts[p]) << 7;
            sMeta[2] = g_mend[p];
        }
    }
    __syncthreads();
    int p = sMeta[0];
    if (p < 0) return;
    int m0 = sMeta[1], mEnd = sMeta[2];
    // decode pair -> (ea, eb_)
    int ea = 0, rem = p, span = NEXP - 1;
    while (rem >= span) { rem -= span; ea++; span--; }
    int eb_ = ea + 1 + rem;
    int nBase = blockIdx.y << 6;   // * 64

    if (tid < CTM) {
        int pp = m0 + tid;
        int pc = pp < mEnd ? pp : mEnd - 1;
        sTok[tid] = g_tok[p][pc];
        sWa[tid]  = g_pwa[p][pc];
        sWb[tid]  = g_pwb[p][pc];
    }
    if (tid < 128) {
        int ex = (tid < 64) ? ea : eb_;
        sBias[tid] = __ldg(eb + ex * HDIM + nBase + (tid & 63));
    }
    __syncthreads();

    // ---- stage loader ----
    int lrow = tid >> 1;
    int lc0  = (tid & 1) * 2;
    size_t gAr = (size_t)sTok[lrow] * HDIM;
    int bexp = (lrow < 64) ? ea : eb_;
    size_t gBr = ((size_t)bexp * HDIM + nBase + (lrow & 63)) * HDIM;

    auto load_stage = [&](int kt, int buf) {
        uint32_t sbase = sb + (uint32_t)buf * STAGEB;
        int kc = kt * CTK;
#pragma unroll
        for (int t = 0; t < 2; t++) {
            int c = lc0 + t;
            uint32_t so = (uint32_t)(lrow * ROWB + c * 16);
            cpa16(sbase + 0 * TILEB + so, g_xh + gAr + kc + c * 8);
            cpa16(sbase + 1 * TILEB + so, g_wh + gBr + kc + c * 8);
        }
    };

    load_stage(0, 0); cp_commit();
    load_stage(1, 1); cp_commit();
    load_stage(2, 2); cp_commit();

    int warp_m = wid >> 1, warp_n = wid & 1;
    int r = lane >> 2, q = lane & 3;

    uint32_t aOff = (uint32_t)((warp_m * 32 + (lane & 15)) * ROWB + ((lane >> 4) << 4));
    uint32_t bLane = (uint32_t)((((lane >> 4) << 3) + (lane & 7)) * ROWB
                                + (((lane >> 3) & 1) << 4));

    float acc[2][2][4][4];
#pragma unroll
    for (int x = 0; x < 2; x++)
#pragma unroll
        for (int mt = 0; mt < 2; mt++)
#pragma unroll
            for (int nt = 0; nt < 4; nt++)
#pragma unroll
                for (int i = 0; i < 4; i++) acc[x][mt][nt][i] = 0.f;

    for (int kt = 0; kt < KT; kt++) {
        int buf = kt & 3;
        if (kt <= KT - 3) cp_wait<2>();
        else if (kt == KT - 2) cp_wait<1>();
        else cp_wait<0>();
        __syncthreads();
        if (kt + 3 < KT) { load_stage(kt + 3, (kt + 3) & 3); cp_commit(); }

        uint32_t tb = sb + (uint32_t)buf * STAGEB;

#pragma unroll
        for (int k16 = 0; k16 < 2; k16++) {
            uint32_t kb = (uint32_t)(k16 * 32);
            uint32_t ah[2][4], bf[2][4][2];
#pragma unroll
            for (int mt = 0; mt < 2; mt++)
                ldsm4(ah[mt], tb + aOff + (uint32_t)(mt * 16 * ROWB) + kb);
#pragma unroll
            for (int x = 0; x < 2; x++)
#pragma unroll
                for (int ntp = 0; ntp < 2; ntp++) {
                    uint32_t regs[4];
                    uint32_t grpRow = (uint32_t)((x * 64 + warp_n * 32 + ntp * 16) * ROWB);
                    ldsm4(regs, tb + TILEB + bLane + grpRow + kb);
                    bf[x][2 * ntp][0] = regs[0]; bf[x][2 * ntp][1] = regs[1];
                    bf[x][2 * ntp + 1][0] = regs[2]; bf[x][2 * ntp + 1][1] = regs[3];
                }
#pragma unroll
            for (int x = 0; x < 2; x++)
#pragma unroll
                for (int mt = 0; mt < 2; mt++)
#pragma unroll
                    for (int nt = 0; nt < 4; nt++)
                        mma16816_f32(acc[x][mt][nt], ah[mt], bf[x][nt]);
        }
    }

    // ---- epilogue: out = wa*(ya+ba) + wb*(yb+bb) ----
#pragma unroll
    for (int mt = 0; mt < 2; mt++) {
        int lr0 = warp_m * 32 + mt * 16 + r;
        int lr1 = lr0 + 8;
        bool v0 = (m0 + lr0) < mEnd;
        bool v1 = (m0 + lr1) < mEnd;
        float wa0 = sWa[lr0], wb0 = sWb[lr0];
        float wa1 = sWa[lr1], wb1 = sWb[lr1];
        float* o0 = out + (size_t)sTok[lr0] * HDIM + nBase;
        float* o1 = out + (size_t)sTok[lr1] * HDIM + nBase;
#pragma unroll
        for (int nt = 0; nt < 4; nt++) {
            int lc = warp_n * 32 + nt * 8 + 2 * q;
            float bax = sBias[lc], bay = sBias[lc + 1];
            float bbx = sBias[64 + lc], bby = sBias[64 + lc + 1];
            if (v0) {
                float2 v;
                v.x = wa0 * (acc[0][mt][nt][0] + bax) + wb0 * (acc[1][mt][nt][0] + bbx);
                v.y = wa0 * (acc[0][mt][nt][1] + bay) + wb0 * (acc[1][mt][nt][1] + bby);
                *(float2*)(o0 + lc) = v;
            }
            if (v1) {
                float2 v;
                v.x = wa1 * (acc[0][mt][nt][2] + bax) + wb1 * (acc[1][mt][nt][2] + bbx);
                v.y = wa1 * (acc[0][mt][nt][3] + bay) + wb1 * (acc[1][mt][nt][3] + bby);
                *(float2*)(o1 + lc) = v;
            }
        }
    }
}

// ---------------- launch ----------------
extern "C" void kernel_launch(void* const* d_in, const int* in_sizes, int n_in,
                              void* d_out, int out_size)
{
    const float* x  = (const float*)d_in[0];
    const float* rw = (const float*)d_in[1];
    const float* rb = (const float*)d_in[2];
    const float* ew = (const float*)d_in[3];
    const float* eb = (const float*)d_in[4];
    float* out = (float*)d_out;
    (void)in_sizes; (void)n_in; (void)out_size;

    cudaFuncSetAttribute(moe_pair, cudaFuncAttributeMaxDynamicSharedMemorySize, SMEM_BYTES);

    prep_kernel<<<RBLK + WBLK, 256>>>(x, rw, rb, ew);
    scan_kernel<<<1, 32>>>();
    moe_pair<<<dim3(MAXT2, HDIM / 64), 256, SMEM_BYTES>>>(eb, out);
}